// round 15
// baseline (speedup 1.0000x reference)
#include <cuda_runtime.h>
#include <cuda_bf16.h>
#include <math.h>

#define BB 64
#define HH 1024
#define EMBD 300
#define VV 50004
#define VV4 12501
#define LL 1024
#define G3H 3072

// split counts
#define SPL_GI 5     // K=300, 64-chunks
#define SPL_GH 8     // K=1024, 128-slices
#define SPL_WY 16    // K=1024, 64-slices
#define SPL_FU 16    // K=2048, 128-slices

#define LBN 128
#define NBLK 391     // logits blocks = ceil(50004/128)
#define NBLKP 392    // padded stride

// ---------------- scratch (static device memory; no allocations) ----------------
__device__ float g_part_gi[SPL_GI * BB * G3H];
__device__ float g_part_gh[SPL_GH * BB * G3H];
__device__ float g_hnew[BB * HH];
__device__ float g_cat[BB * 2 * HH];       // [context | h_new]
__device__ float g_part_wy[SPL_WY * BB * HH];
__device__ float g_xwy[BB * LL];
__device__ float g_pm[BB * 16];
__device__ float g_ps[BB * 16];
__device__ float g_pctx[BB * 16 * HH];
__device__ float g_part_fu[SPL_FU * BB * HH];
__device__ __nv_bfloat16 g_fused_b16[BB * HH];
__device__ float g_lsm[BB * NBLKP];
__device__ float g_lss[BB * NBLKP];

__device__ __forceinline__ float to_tf32(float x)
{
    float r;
    asm("cvt.rna.tf32.f32 %0, %1;" : "=f"(r) : "f"(x));
    return r;
}

__device__ __forceinline__ float4 f4_add(float4 a, float4 b)
{
    return make_float4(a.x + b.x, a.y + b.y, a.z + b.z, a.w + b.w);
}

__device__ __forceinline__ void lse_upd(float& m, float& s, float v)
{
    float nm = fmaxf(m, v);
    s = s * __expf(m - nm) + __expf(v - nm);
    m = nm;
}

__device__ __forceinline__ void lse_merge(float& m, float& s, float m2, float s2)
{
    float nm = fmaxf(m, m2);
    s = s * __expf(m - nm) + s2 * __expf(m2 - nm);
    m = nm;
}

__device__ __forceinline__ uint2 f4_to_bf16x4(float4 v)
{
    __nv_bfloat162 p0 = __floats2bfloat162_rn(v.x, v.y);
    __nv_bfloat162 p1 = __floats2bfloat162_rn(v.z, v.w);
    uint2 pk;
    pk.x = *(unsigned int*)&p0;
    pk.y = *(unsigned int*)&p1;
    return pk;
}

// ---------------- 3xTF32 tensor-core GEMM (small GEMMs, near-fp32 accuracy) ----------------
// Register-prefetch double buffering (R14 win): these kernels run at 1 block/SM.
__device__ __forceinline__ void tf32_gemm(
    const float* __restrict__ A, int lda,
    const int* __restrict__ inp, const float* __restrict__ emb, bool gather,
    const float* __restrict__ W, int ldw, int N,
    float* __restrict__ Cpart, int ks0, int ks1)
{
    __shared__ float As[2][64][36];
    __shared__ float Ws[2][128][36];

    const int tid  = threadIdx.x;
    const int lane = tid & 31;
    const int wid  = tid >> 5;
    const int nb   = blockIdx.x * 128;
    const int warp_m = wid >> 2;
    const int warp_n = wid & 3;
    const int g = lane >> 2;
    const int q = lane & 3;

    const int arow0 = (tid      ) >> 3, ac0 = (tid      ) & 7;
    const int arow1 = (tid + 256) >> 3, ac1 = (tid + 256) & 7;
    const int wrow0 = (tid      ) >> 3, wc0 = (tid      ) & 7;
    const int wrow1 = (tid + 256) >> 3, wc1 = (tid + 256) & 7;
    const int wrow2 = (tid + 512) >> 3, wc2 = (tid + 512) & 7;
    const int wrow3 = (tid + 768) >> 3, wc3 = (tid + 768) & 7;

    float acc[2][4][4];
#pragma unroll
    for (int tm = 0; tm < 2; tm++)
#pragma unroll
        for (int tn = 0; tn < 4; tn++)
#pragma unroll
            for (int c = 0; c < 4; c++) acc[tm][tn][c] = 0.f;

    float4 pa[2], pw[4];

#define LOAD_A_ELEM(slot, arow, ac)                                              \
    do {                                                                         \
        int k0_ = kbn + (ac) * 4;                                                \
        float4 v_ = make_float4(0.f, 0.f, 0.f, 0.f);                             \
        if (k0_ + 4 <= ks1) {                                                    \
            const float* ap_ = gather ? (emb + (size_t)inp[arow] * lda)          \
                                      : (A + (size_t)(arow) * lda);              \
            v_ = *(const float4*)(ap_ + k0_);                                    \
        }                                                                        \
        pa[slot] = v_;                                                           \
    } while (0)

#define LOAD_W_ELEM(slot, wrow, wc)                                              \
    do {                                                                         \
        int k0_ = kbn + (wc) * 4;                                                \
        int n_  = nb + (wrow);                                                   \
        float4 v_ = make_float4(0.f, 0.f, 0.f, 0.f);                             \
        if (n_ < N && k0_ + 4 <= ks1)                                            \
            v_ = *(const float4*)(W + (size_t)n_ * ldw + k0_);                   \
        pw[slot] = v_;                                                           \
    } while (0)

#define LOAD_ALL()                                                               \
    do {                                                                         \
        LOAD_A_ELEM(0, arow0, ac0);                                              \
        LOAD_A_ELEM(1, arow1, ac1);                                              \
        LOAD_W_ELEM(0, wrow0, wc0);                                              \
        LOAD_W_ELEM(1, wrow1, wc1);                                              \
        LOAD_W_ELEM(2, wrow2, wc2);                                              \
        LOAD_W_ELEM(3, wrow3, wc3);                                              \
    } while (0)

#define STORE_A(slot, arow, ac)                                                  \
    do {                                                                         \
        float4 v_ = pa[slot];                                                    \
        float hx_ = to_tf32(v_.x), hy_ = to_tf32(v_.y),                          \
              hz_ = to_tf32(v_.z), hw_ = to_tf32(v_.w);                          \
        As[0][arow][(ac) * 4 + 0] = hx_;                                         \
        As[0][arow][(ac) * 4 + 1] = hy_;                                         \
        As[0][arow][(ac) * 4 + 2] = hz_;                                         \
        As[0][arow][(ac) * 4 + 3] = hw_;                                         \
        As[1][arow][(ac) * 4 + 0] = to_tf32(v_.x - hx_);                         \
        As[1][arow][(ac) * 4 + 1] = to_tf32(v_.y - hy_);                         \
        As[1][arow][(ac) * 4 + 2] = to_tf32(v_.z - hz_);                         \
        As[1][arow][(ac) * 4 + 3] = to_tf32(v_.w - hw_);                         \
    } while (0)

#define STORE_W(slot, wrow, wc)                                                  \
    do {                                                                         \
        float4 v_ = pw[slot];                                                    \
        float hx_ = to_tf32(v_.x), hy_ = to_tf32(v_.y),                          \
              hz_ = to_tf32(v_.z), hw_ = to_tf32(v_.w);                          \
        Ws[0][wrow][(wc) * 4 + 0] = hx_;                                         \
        Ws[0][wrow][(wc) * 4 + 1] = hy_;                                         \
        Ws[0][wrow][(wc) * 4 + 2] = hz_;                                         \
        Ws[0][wrow][(wc) * 4 + 3] = hw_;                                         \
        Ws[1][wrow][(wc) * 4 + 0] = to_tf32(v_.x - hx_);                         \
        Ws[1][wrow][(wc) * 4 + 1] = to_tf32(v_.y - hy_);                         \
        Ws[1][wrow][(wc) * 4 + 2] = to_tf32(v_.z - hz_);                         \
        Ws[1][wrow][(wc) * 4 + 3] = to_tf32(v_.w - hw_);                         \
    } while (0)

    {
        int kbn = ks0;
        LOAD_ALL();
    }

    for (int kb = ks0; kb < ks1; kb += 32) {
        STORE_A(0, arow0, ac0);
        STORE_A(1, arow1, ac1);
        STORE_W(0, wrow0, wc0);
        STORE_W(1, wrow1, wc1);
        STORE_W(2, wrow2, wc2);
        STORE_W(3, wrow3, wc3);
        __syncthreads();

        if (kb + 32 < ks1) {
            int kbn = kb + 32;
            LOAD_ALL();
        }

#pragma unroll
        for (int kk = 0; kk < 32; kk += 8) {
            unsigned int ah[2][4], al[2][4];
#pragma unroll
            for (int tm = 0; tm < 2; tm++) {
                int m = warp_m * 32 + tm * 16;
                ah[tm][0] = __float_as_uint(As[0][m + g    ][kk + q    ]);
                ah[tm][1] = __float_as_uint(As[0][m + g + 8][kk + q    ]);
                ah[tm][2] = __float_as_uint(As[0][m + g    ][kk + q + 4]);
                ah[tm][3] = __float_as_uint(As[0][m + g + 8][kk + q + 4]);
                al[tm][0] = __float_as_uint(As[1][m + g    ][kk + q    ]);
                al[tm][1] = __float_as_uint(As[1][m + g + 8][kk + q    ]);
                al[tm][2] = __float_as_uint(As[1][m + g    ][kk + q + 4]);
                al[tm][3] = __float_as_uint(As[1][m + g + 8][kk + q + 4]);
            }
#pragma unroll
            for (int tn = 0; tn < 4; tn++) {
                int n = warp_n * 32 + tn * 8 + g;
                unsigned int bh0 = __float_as_uint(Ws[0][n][kk + q    ]);
                unsigned int bh1 = __float_as_uint(Ws[0][n][kk + q + 4]);
                unsigned int bl0 = __float_as_uint(Ws[1][n][kk + q    ]);
                unsigned int bl1 = __float_as_uint(Ws[1][n][kk + q + 4]);
#pragma unroll
                for (int tm = 0; tm < 2; tm++) {
                    asm volatile(
                        "mma.sync.aligned.m16n8k8.row.col.f32.tf32.tf32.f32 "
                        "{%0,%1,%2,%3}, {%4,%5,%6,%7}, {%8,%9}, {%0,%1,%2,%3};\n"
                        : "+f"(acc[tm][tn][0]), "+f"(acc[tm][tn][1]),
                          "+f"(acc[tm][tn][2]), "+f"(acc[tm][tn][3])
                        : "r"(al[tm][0]), "r"(al[tm][1]), "r"(al[tm][2]), "r"(al[tm][3]),
                          "r"(bh0), "r"(bh1));
                    asm volatile(
                        "mma.sync.aligned.m16n8k8.row.col.f32.tf32.tf32.f32 "
                        "{%0,%1,%2,%3}, {%4,%5,%6,%7}, {%8,%9}, {%0,%1,%2,%3};\n"
                        : "+f"(acc[tm][tn][0]), "+f"(acc[tm][tn][1]),
                          "+f"(acc[tm][tn][2]), "+f"(acc[tm][tn][3])
                        : "r"(ah[tm][0]), "r"(ah[tm][1]), "r"(ah[tm][2]), "r"(ah[tm][3]),
                          "r"(bl0), "r"(bl1));
                    asm volatile(
                        "mma.sync.aligned.m16n8k8.row.col.f32.tf32.tf32.f32 "
                        "{%0,%1,%2,%3}, {%4,%5,%6,%7}, {%8,%9}, {%0,%1,%2,%3};\n"
                        : "+f"(acc[tm][tn][0]), "+f"(acc[tm][tn][1]),
                          "+f"(acc[tm][tn][2]), "+f"(acc[tm][tn][3])
                        : "r"(ah[tm][0]), "r"(ah[tm][1]), "r"(ah[tm][2]), "r"(ah[tm][3]),
                          "r"(bh0), "r"(bh1));
                }
            }
        }
        __syncthreads();
    }

#undef LOAD_A_ELEM
#undef LOAD_W_ELEM
#undef LOAD_ALL
#undef STORE_A
#undef STORE_W

#pragma unroll
    for (int tm = 0; tm < 2; tm++) {
#pragma unroll
        for (int tn = 0; tn < 4; tn++) {
            int m0 = warp_m * 32 + tm * 16 + g;
            int n  = nb + warp_n * 32 + tn * 8 + q * 2;
            if (n < N) {
                *(float2*)(Cpart + (size_t)m0 * N + n) =
                    make_float2(acc[tm][tn][0], acc[tm][tn][1]);
                *(float2*)(Cpart + (size_t)(m0 + 8) * N + n) =
                    make_float2(acc[tm][tn][2], acc[tm][tn][3]);
            }
        }
    }
}

// ---------------- kernels ----------------
__global__ void __launch_bounds__(256) k_gru_gemm(
    const int* __restrict__ input, const float* __restrict__ emb,
    const float* __restrict__ hidden,
    const float* __restrict__ w_ih, const float* __restrict__ w_hh)
{
    int split = blockIdx.y;
    if (blockIdx.z == 0) {
        if (split >= SPL_GI) return;
        int ks0 = split * 64;
        int ks1 = min(ks0 + 64, EMBD);
        tf32_gemm(nullptr, EMBD, input, emb, true, w_ih, EMBD, G3H,
                  g_part_gi + (size_t)split * BB * G3H, ks0, ks1);
    } else {
        int ks0 = split * 128;
        int ks1 = ks0 + 128;
        tf32_gemm(hidden, HH, nullptr, nullptr, false, w_hh, HH, G3H,
                  g_part_gh + (size_t)split * BB * G3H, ks0, ks1);
    }
}

// GRU combine + gate math: float2, grid 128, block 256 (32768 threads)
__global__ void __launch_bounds__(256) k_gru(
    const float* __restrict__ hidden,
    const float* __restrict__ b_ih, const float* __restrict__ b_hh,
    float* __restrict__ out_hid)
{
    int idx2 = blockIdx.x * 256 + threadIdx.x;     // 0..32767
    int b  = idx2 >> 9;
    int j  = (idx2 & 511) * 2;

    float2 gir = *(const float2*)(b_ih + j);
    float2 giz = *(const float2*)(b_ih + j + HH);
    float2 gin = *(const float2*)(b_ih + j + 2 * HH);
    float2 ghr = *(const float2*)(b_hh + j);
    float2 ghz = *(const float2*)(b_hh + j + HH);
    float2 ghn = *(const float2*)(b_hh + j + 2 * HH);

#pragma unroll
    for (int s = 0; s < SPL_GI; s++) {
        const float* pi = g_part_gi + (size_t)s * BB * G3H + (size_t)b * G3H;
        float2 a = *(const float2*)(pi + j);
        float2 c = *(const float2*)(pi + j + HH);
        float2 d = *(const float2*)(pi + j + 2 * HH);
        gir.x += a.x; gir.y += a.y;
        giz.x += c.x; giz.y += c.y;
        gin.x += d.x; gin.y += d.y;
    }
#pragma unroll
    for (int s = 0; s < SPL_GH; s++) {
        const float* ph = g_part_gh + (size_t)s * BB * G3H + (size_t)b * G3H;
        float2 a = *(const float2*)(ph + j);
        float2 c = *(const float2*)(ph + j + HH);
        float2 d = *(const float2*)(ph + j + 2 * HH);
        ghr.x += a.x; ghr.y += a.y;
        ghz.x += c.x; ghz.y += c.y;
        ghn.x += d.x; ghn.y += d.y;
    }

    float2 hv = *(const float2*)(hidden + (size_t)b * HH + j);
    float2 hn;
    {
        float r0 = 1.f / (1.f + __expf(-(gir.x + ghr.x)));
        float z0 = 1.f / (1.f + __expf(-(giz.x + ghz.x)));
        float n0 = tanhf(gin.x + r0 * ghn.x);
        hn.x = (1.f - z0) * n0 + z0 * hv.x;
        float r1 = 1.f / (1.f + __expf(-(gir.y + ghr.y)));
        float z1 = 1.f / (1.f + __expf(-(giz.y + ghz.y)));
        float n1 = tanhf(gin.y + r1 * ghn.y);
        hn.y = (1.f - z1) * n1 + z1 * hv.y;
    }
    *(float2*)(g_hnew + (size_t)b * HH + j)         = hn;
    *(float2*)(g_cat + (size_t)b * 2 * HH + HH + j) = hn;
    *(float2*)(out_hid + (size_t)b * HH + j)        = hn;
}

__global__ void __launch_bounds__(256) k_gemm_wy(const float* __restrict__ w_attn)
{
    int split = blockIdx.y;
    int ks0 = split * 64;
    tf32_gemm(g_hnew, HH, nullptr, nullptr, false, w_attn, HH, HH,
              g_part_wy + (size_t)split * BB * HH, ks0, ks0 + 64);
}

// attention pass 1 with fused Wy combine: grid (16 chunks, 64 b), 256 threads
// R8-exact: wy in registers, rolled outer loop, in-loop mask load.
__global__ void __launch_bounds__(256) k_attn1(
    const float* __restrict__ src, const int* __restrict__ mask,
    const float* __restrict__ b_attn)
{
    int b = blockIdx.y;
    int chunk = blockIdx.x;
    int l0 = chunk * 64;
    int tid = threadIdx.x, lane = tid & 31, wid = tid >> 5;

    __shared__ float swy[1024];
    __shared__ float sm[8], ss[8];
    __shared__ float sctx[8][1024];

    {
        int h = tid * 4;
        float4 v = *(const float4*)(b_attn + h);
#pragma unroll
        for (int s = 0; s < SPL_WY; s++)
            v = f4_add(v, *(const float4*)(g_part_wy + (size_t)s * BB * HH
                                            + (size_t)b * HH + h));
        *(float4*)&swy[h] = v;
    }
    __syncthreads();

    float4 wyv[8];
#pragma unroll
    for (int qq = 0; qq < 8; qq++)
        wyv[qq] = *(const float4*)&swy[4 * lane + 128 * qq];

    float m = -1e30f, s = 0.f;
    float4 acc[8];
#pragma unroll
    for (int qq = 0; qq < 8; qq++) acc[qq] = make_float4(0.f, 0.f, 0.f, 0.f);

    for (int i = 0; i < 8; i++) {
        int l = l0 + wid * 8 + i;
        const float* sp = src + ((size_t)l * BB + b) * HH;
        float4 v[8];
#pragma unroll
        for (int qq = 0; qq < 8; qq++)
            v[qq] = *(const float4*)(sp + 4 * lane + 128 * qq);
        float d = 0.f;
#pragma unroll
        for (int qq = 0; qq < 8; qq++) {
            d = fmaf(v[qq].x, wyv[qq].x, d);
            d = fmaf(v[qq].y, wyv[qq].y, d);
            d = fmaf(v[qq].z, wyv[qq].z, d);
            d = fmaf(v[qq].w, wyv[qq].w, d);
        }
#pragma unroll
        for (int o = 16; o > 0; o >>= 1) d += __shfl_xor_sync(0xffffffffu, d, o);
        if (mask[(size_t)b * LL + l] != 0) d = -1e30f;
        if (lane == 0) g_xwy[(size_t)b * LL + l] = d;

        float nm = fmaxf(m, d);
        float sc = __expf(m - nm);
        float p  = __expf(d - nm);
        s = s * sc + p;
#pragma unroll
        for (int qq = 0; qq < 8; qq++) {
            acc[qq].x = acc[qq].x * sc + p * v[qq].x;
            acc[qq].y = acc[qq].y * sc + p * v[qq].y;
            acc[qq].z = acc[qq].z * sc + p * v[qq].z;
            acc[qq].w = acc[qq].w * sc + p * v[qq].w;
        }
        m = nm;
    }

    if (lane == 0) { sm[wid] = m; ss[wid] = s; }
    __syncthreads();
    float M = sm[0];
#pragma unroll
    for (int w = 1; w < 8; w++) M = fmaxf(M, sm[w]);
    float S = 0.f;
#pragma unroll
    for (int w = 0; w < 8; w++) S += ss[w] * __expf(sm[w] - M);

    float f = __expf(m - M);
#pragma unroll
    for (int qq = 0; qq < 8; qq++) {
        float4 t = acc[qq];
        t.x *= f; t.y *= f; t.z *= f; t.w *= f;
        *(float4*)&sctx[wid][4 * lane + 128 * qq] = t;
    }
    __syncthreads();

    int h0 = tid * 4;
    float4 tot = make_float4(0.f, 0.f, 0.f, 0.f);
#pragma unroll
    for (int w = 0; w < 8; w++) {
        float4 t = *(const float4*)&sctx[w][h0];
        tot.x += t.x; tot.y += t.y; tot.z += t.z; tot.w += t.w;
    }
    int pidx = b * 16 + chunk;
    *(float4*)(g_pctx + (size_t)pidx * HH + h0) = tot;
    if (tid == 0) { g_pm[pidx] = M; g_ps[pidx] = S; }
}

__global__ void k_attn2(float* __restrict__ out_scores)
{
    int b = blockIdx.x, t = threadIdx.x;
    __shared__ float fac[16];
    __shared__ float sM, sInvZ;
    if (t == 0) {
        float M = g_pm[b * 16];
        for (int c = 1; c < 16; c++) M = fmaxf(M, g_pm[b * 16 + c]);
        float Z = 0.f;
        for (int c = 0; c < 16; c++) Z += g_ps[b * 16 + c] * __expf(g_pm[b * 16 + c] - M);
        float invZ = 1.f / Z;
        for (int c = 0; c < 16; c++) fac[c] = __expf(g_pm[b * 16 + c] - M) * invZ;
        sM = M; sInvZ = invZ;
    }
    __syncthreads();

    int h0 = t * 4;
    float4 tot = make_float4(0.f, 0.f, 0.f, 0.f);
#pragma unroll
    for (int c = 0; c < 16; c++) {
        float4 v = *(const float4*)(g_pctx + (size_t)(b * 16 + c) * HH + h0);
        float fc = fac[c];
        tot.x += v.x * fc; tot.y += v.y * fc; tot.z += v.z * fc; tot.w += v.w * fc;
    }
    *(float4*)(g_cat + (size_t)b * 2 * HH + h0) = tot;

    float M = sM, invZ = sInvZ;
#pragma unroll
    for (int r = 0; r < 4; r++) {
        int l = t + 256 * r;
        float sc = __expf(g_xwy[(size_t)b * LL + l] - M) * invZ;
        out_scores[(size_t)b * LL + l] = sc;
    }
}

__global__ void __launch_bounds__(256) k_gemm_fu(const float* __restrict__ w_lin)
{
    int split = blockIdx.y;
    int ks0 = split * 128;
    tf32_gemm(g_cat, 2 * HH, nullptr, nullptr, false, w_lin, 2 * HH, HH,
              g_part_fu + (size_t)split * BB * HH, ks0, ks0 + 128);
}

// combine + tanh + bf16: float2, grid 128, block 256 (32768 threads)
__global__ void __launch_bounds__(256) k_combine_fu(const float* __restrict__ b_lin)
{
    int idx2 = blockIdx.x * 256 + threadIdx.x;
    int j = (idx2 & 511) * 2;
    int off = (idx2 >> 9) * HH + j;
    float2 v = *(const float2*)(b_lin + j);
#pragma unroll
    for (int s = 0; s < SPL_FU; s++) {
        float2 p = *(const float2*)(g_part_fu + (size_t)s * BB * HH + off);
        v.x += p.x; v.y += p.y;
    }
    __nv_bfloat162 pk = __floats2bfloat162_rn(tanhf(v.x), tanhf(v.y));
    *(unsigned int*)(g_fused_b16 + off) = *(unsigned int*)&pk;
}

// ---------------- logits GEMM on tensor cores (bf16, BN=128) + fused per-block LSE ----
// W converted to bf16 AT LOAD (prefetch regs are bf16: 16 regs instead of 32)
// -> ~80 regs -> 3 blocks/SM -> 444 slots >= 391 blocks: single wave, no tail.
#define LBK 64
#define WPAD 72

__global__ void __launch_bounds__(256, 3) k_logits_mma(
    const float* __restrict__ w_out, const float* __restrict__ b_out,
    float* __restrict__ out_logp)
{
    __shared__ __nv_bfloat16 As[64][WPAD];
    __shared__ __nv_bfloat16 Ws[LBN][WPAD];
    __shared__ float sRm[4][64], sRs[4][64];

    const int tid  = threadIdx.x;
    const int lane = tid & 31;
    const int wid  = tid >> 5;
    const int nb   = blockIdx.x * LBN;
    const int warp_m = wid >> 2;
    const int warp_n = wid & 3;
    const int g = lane >> 2;
    const int q = lane & 3;

    float acc[2][4][4];
#pragma unroll
    for (int tm = 0; tm < 2; tm++)
#pragma unroll
        for (int tn = 0; tn < 4; tn++)
#pragma unroll
            for (int c = 0; c < 4; c++) acc[tm][tn][c] = 0.f;

    const int ar = tid >> 2;
    const int as = tid & 3;
    const int wr = tid >> 2;
    const int wc = tid & 3;

    uint4 pa0, pa1;
    uint2 pwb[8];          // bf16x4 per slot (converted at load)

    {
        const uint4* s4 = (const uint4*)(g_fused_b16 + (size_t)ar * HH + as * 16);
        pa0 = s4[0]; pa1 = s4[1];
#pragma unroll
        for (int half = 0; half < 2; half++) {
            int n = nb + wr + half * 64;
            const float* wp = w_out + (size_t)n * HH;
            bool ok = (n < VV);
#pragma unroll
            for (int j = 0; j < 4; j++) {
                int f4 = wc + j * 4;
                float4 v = ok ? *(const float4*)(wp + f4 * 4)
                              : make_float4(0.f, 0.f, 0.f, 0.f);
                pwb[half * 4 + j] = f4_to_bf16x4(v);
            }
        }
    }

    for (int kb = 0; kb < HH; kb += LBK) {
        *(uint4*)(&As[ar][as * 16])     = pa0;
        *(uint4*)(&As[ar][as * 16 + 8]) = pa1;
#pragma unroll
        for (int half = 0; half < 2; half++) {
#pragma unroll
            for (int j = 0; j < 4; j++) {
                int f4 = wc + j * 4;
                *(uint2*)(&Ws[wr + half * 64][f4 * 4]) = pwb[half * 4 + j];
            }
        }
        __syncthreads();

        if (kb + LBK < HH) {
            int kn = kb + LBK;
            const uint4* s4 = (const uint4*)(g_fused_b16 + (size_t)ar * HH + kn + as * 16);
            pa0 = s4[0]; pa1 = s4[1];
#pragma unroll
            for (int half = 0; half < 2; half++) {
                int n = nb + wr + half * 64;
                const float* wp = w_out + (size_t)n * HH + kn;
                bool ok = (n < VV);
#pragma unroll
                for (int j = 0; j < 4; j++) {
                    int f4 = wc + j * 4;
                    float4 v = ok ? *(const float4*)(wp + f4 * 4)
                                  : make_float4(0.f, 0.f, 0.f, 0.f);
                    pwb[half * 4 + j] = f4_to_bf16x4(v);
                }
            }
        }

#pragma unroll
        for (int kk = 0; kk < LBK; kk += 16) {
            unsigned int a[2][4];
#pragma unroll
            for (int tm = 0; tm < 2; tm++) {
                int m = warp_m * 32 + tm * 16;
                a[tm][0] = *(const unsigned int*)&As[m + g    ][kk + q * 2];
                a[tm][1] = *(const unsigned int*)&As[m + g + 8][kk + q * 2];
                a[tm][2] = *(const unsigned int*)&As[m + g    ][kk + 8 + q * 2];
                a[tm][3] = *(const unsigned int*)&As[m + g + 8][kk + 8 + q * 2];
            }
#pragma unroll
            for (int tn = 0; tn < 4; tn++) {
                int n = warp_n * 32 + tn * 8;
                unsigned int b0 = *(const unsigned int*)&Ws[n + g][kk + q * 2];
                unsigned int b1 = *(const unsigned int*)&Ws[n + g][kk + 8 + q * 2];
#pragma unroll
                for (int tm = 0; tm < 2; tm++) {
                    asm volatile(
                        "mma.sync.aligned.m16n8k16.row.col.f32.bf16.bf16.f32 "
                        "{%0,%1,%2,%3}, {%4,%5,%6,%7}, {%8,%9}, {%0,%1,%2,%3};\n"
                        : "+f"(acc[tm][tn][0]), "+f"(acc[tm][tn][1]),
                          "+f"(acc[tm][tn][2]), "+f"(acc[tm][tn][3])
                        : "r"(a[tm][0]), "r"(a[tm][1]), "r"(a[tm][2]), "r"(a[tm][3]),
                          "r"(b0), "r"(b1));
                }
            }
        }
        __syncthreads();
    }

    // epilogue: bias + store + per-row partial logsumexp over this block's 128 cols
    float rm[4], rs[4];
#pragma unroll
    for (int k = 0; k < 4; k++) { rm[k] = -1e30f; rs[k] = 0.f; }

#pragma unroll
    for (int tm = 0; tm < 2; tm++) {
#pragma unroll
        for (int tn = 0; tn < 4; tn++) {
            int m0 = warp_m * 32 + tm * 16 + g;
            int n  = nb + warp_n * 32 + tn * 8 + q * 2;
            bool ok0 = (n < VV), ok1 = (n + 1 < VV);
            float bz0 = ok0 ? b_out[n] : 0.f;
            float bz1 = ok1 ? b_out[n + 1] : 0.f;
            float v00 = acc[tm][tn][0] + bz0, v01 = acc[tm][tn][1] + bz1;
            float v10 = acc[tm][tn][2] + bz0, v11 = acc[tm][tn][3] + bz1;
            if (ok1) {
                *(float2*)(out_logp + (size_t)m0 * VV + n)       = make_float2(v00, v01);
                *(float2*)(out_logp + (size_t)(m0 + 8) * VV + n) = make_float2(v10, v11);
            } else if (ok0) {
                out_logp[(size_t)m0 * VV + n]       = v00;
                out_logp[(size_t)(m0 + 8) * VV + n] = v10;
            }
            int k0 = tm * 2, k1 = tm * 2 + 1;
            if (ok0) { lse_upd(rm[k0], rs[k0], v00); lse_upd(rm[k1], rs[k1], v10); }
            if (ok1) { lse_upd(rm[k0], rs[k0], v01); lse_upd(rm[k1], rs[k1], v11); }
        }
    }

#pragma unroll
    for (int k = 0; k < 4; k++) {
#pragma unroll
        for (int o = 1; o <= 2; o <<= 1) {
            float m2 = __shfl_xor_sync(0xffffffffu, rm[k], o);
            float s2 = __shfl_xor_sync(0xffffffffu, rs[k], o);
            lse_merge(rm[k], rs[k], m2, s2);
        }
    }
    if (q == 0) {
#pragma unroll
        for (int k = 0; k < 4; k++) {
            int row = warp_m * 32 + (k >> 1) * 16 + (k & 1) * 8 + g;
            sRm[warp_n][row] = rm[k];
            sRs[warp_n][row] = rs[k];
        }
    }
    __syncthreads();
    if (tid < 64) {
        float M = sRm[0][tid], S = sRs[0][tid];
#pragma unroll
        for (int w = 1; w < 4; w++) lse_merge(M, S, sRm[w][tid], sRs[w][tid]);
        g_lsm[(size_t)tid * NBLKP + blockIdx.x] = M;
        g_lss[(size_t)tid * NBLKP + blockIdx.x] = S;
    }
}

// final: reduce the NBLK per-block LSE partials, subtract. grid (49, 64), block 256
__global__ void k_sub(float* __restrict__ logp)
{
    __shared__ float slse;
    __shared__ float smW[8], ssW[8];
    int b = blockIdx.y;
    int t = threadIdx.x;

    float m = -1e30f, s = 0.f;
    for (int i = t; i < NBLK; i += 256)
        lse_merge(m, s, g_lsm[(size_t)b * NBLKP + i], g_lss[(size_t)b * NBLKP + i]);
#pragma unroll
    for (int o = 16; o > 0; o >>= 1) {
        float m2 = __shfl_xor_sync(0xffffffffu, m, o);
        float s2 = __shfl_xor_sync(0xffffffffu, s, o);
        lse_merge(m, s, m2, s2);
    }
    int lane = t & 31, wid = t >> 5;
    if (lane == 0) { smW[wid] = m; ssW[wid] = s; }
    __syncthreads();
    if (t == 0) {
        float M = smW[0], S = ssW[0];
#pragma unroll
        for (int w = 1; w < 8; w++) lse_merge(M, S, smW[w], ssW[w]);
        slse = M + logf(S);
    }
    __syncthreads();

    int n4 = blockIdx.x * 256 + t;
    if (n4 < VV4) {
        float l = slse;
        float4* p = (float4*)(logp + (size_t)b * VV) + n4;
        float4 v = *p;
        v.x -= l; v.y -= l; v.z -= l; v.w -= l;
        *p = v;
    }
}

// ---------------- launcher ----------------
extern "C" void kernel_launch(void* const* d_in, const int* in_sizes, int n_in,
                              void* d_out, int out_size)
{
    const int*   input  = (const int*)  d_in[0];
    const float* hidden = (const float*)d_in[1];
    const float* src    = (const float*)d_in[2];
    const int*   mask   = (const int*)  d_in[3];
    const float* emb    = (const float*)d_in[4];
    const float* w_ih   = (const float*)d_in[5];
    const float* w_hh   = (const float*)d_in[6];
    const float* b_ih   = (const float*)d_in[7];
    const float* b_hh   = (const float*)d_in[8];
    const float* w_attn = (const float*)d_in[9];
    const float* b_attn = (const float*)d_in[10];
    const float* w_lin  = (const float*)d_in[11];
    const float* b_lin  = (const float*)d_in[12];
    const float* w_out  = (const float*)d_in[13];
    const float* b_out  = (const float*)d_in[14];

    float* out        = (float*)d_out;
    float* out_logp   = out;                                   // [64 x 50004]
    float* out_hid    = out + (size_t)BB * VV;                 // [1 x 64 x 1024]
    float* out_scores = out_hid + (size_t)BB * HH;             // [64 x 1024]

    k_gru_gemm<<<dim3(24, 8, 2), 256>>>(input, emb, hidden, w_ih, w_hh);
    k_gru<<<128, 256>>>(hidden, b_ih, b_hh, out_hid);
    k_gemm_wy<<<dim3(8, SPL_WY), 256>>>(w_attn);
    k_attn1<<<dim3(16, BB), 256>>>(src, mask, b_attn);
    k_attn2<<<BB, 256>>>(out_scores);
    k_gemm_fu<<<dim3(8, SPL_FU), 256>>>(w_lin);
    k_combine_fu<<<128, 256>>>(b_lin);
    k_logits_mma<<<NBLK, 256>>>(w_out, b_out, out_logp);
    k_sub<<<dim3((VV4 + 255) / 256, BB), 256>>>(out_logp);
}

// round 16
// speedup vs baseline: 1.0249x; 1.0249x over previous
#include <cuda_runtime.h>
#include <cuda_bf16.h>
#include <math.h>

#define BB 64
#define HH 1024
#define EMBD 300
#define VV 50004
#define VV4 12501
#define LL 1024
#define G3H 3072

// split counts
#define SPL_GI 5     // K=300, 64-chunks
#define SPL_GH 8     // K=1024, 128-slices
#define SPL_WY 16    // K=1024, 64-slices
#define SPL_FU 16    // K=2048, 128-slices

#define LBN 128
#define NBLK 391     // logits blocks = ceil(50004/128)
#define NBLKP 392    // padded stride

// ---------------- scratch (static device memory; no allocations) ----------------
__device__ float g_part_gi[SPL_GI * BB * G3H];
__device__ float g_part_gh[SPL_GH * BB * G3H];
__device__ float g_hnew[BB * HH];
__device__ float g_cat[BB * 2 * HH];       // [context | h_new]
__device__ float g_part_wy[SPL_WY * BB * HH];
__device__ float g_xwy[BB * LL];
__device__ float g_pm[BB * 16];
__device__ float g_ps[BB * 16];
__device__ float g_pctx[BB * 16 * HH];
__device__ float g_part_fu[SPL_FU * BB * HH];
__device__ __nv_bfloat16 g_fused_b16[BB * HH];
__device__ float g_lsm[BB * NBLKP];
__device__ float g_lss[BB * NBLKP];

__device__ __forceinline__ float to_tf32(float x)
{
    float r;
    asm("cvt.rna.tf32.f32 %0, %1;" : "=f"(r) : "f"(x));
    return r;
}

__device__ __forceinline__ float4 f4_add(float4 a, float4 b)
{
    return make_float4(a.x + b.x, a.y + b.y, a.z + b.z, a.w + b.w);
}

__device__ __forceinline__ void lse_upd(float& m, float& s, float v)
{
    float nm = fmaxf(m, v);
    s = s * __expf(m - nm) + __expf(v - nm);
    m = nm;
}

__device__ __forceinline__ void lse_merge(float& m, float& s, float m2, float s2)
{
    float nm = fmaxf(m, m2);
    s = s * __expf(m - nm) + s2 * __expf(m2 - nm);
    m = nm;
}

// ---------------- 3xTF32 tensor-core GEMM (small GEMMs, near-fp32 accuracy) ----------------
// Register-prefetch double buffering (R14 win): these kernels run at 1 block/SM.
__device__ __forceinline__ void tf32_gemm(
    const float* __restrict__ A, int lda,
    const int* __restrict__ inp, const float* __restrict__ emb, bool gather,
    const float* __restrict__ W, int ldw, int N,
    float* __restrict__ Cpart, int ks0, int ks1)
{
    __shared__ float As[2][64][36];
    __shared__ float Ws[2][128][36];

    const int tid  = threadIdx.x;
    const int lane = tid & 31;
    const int wid  = tid >> 5;
    const int nb   = blockIdx.x * 128;
    const int warp_m = wid >> 2;
    const int warp_n = wid & 3;
    const int g = lane >> 2;
    const int q = lane & 3;

    const int arow0 = (tid      ) >> 3, ac0 = (tid      ) & 7;
    const int arow1 = (tid + 256) >> 3, ac1 = (tid + 256) & 7;
    const int wrow0 = (tid      ) >> 3, wc0 = (tid      ) & 7;
    const int wrow1 = (tid + 256) >> 3, wc1 = (tid + 256) & 7;
    const int wrow2 = (tid + 512) >> 3, wc2 = (tid + 512) & 7;
    const int wrow3 = (tid + 768) >> 3, wc3 = (tid + 768) & 7;

    float acc[2][4][4];
#pragma unroll
    for (int tm = 0; tm < 2; tm++)
#pragma unroll
        for (int tn = 0; tn < 4; tn++)
#pragma unroll
            for (int c = 0; c < 4; c++) acc[tm][tn][c] = 0.f;

    float4 pa[2], pw[4];

#define LOAD_A_ELEM(slot, arow, ac)                                              \
    do {                                                                         \
        int k0_ = kbn + (ac) * 4;                                                \
        float4 v_ = make_float4(0.f, 0.f, 0.f, 0.f);                             \
        if (k0_ + 4 <= ks1) {                                                    \
            const float* ap_ = gather ? (emb + (size_t)inp[arow] * lda)          \
                                      : (A + (size_t)(arow) * lda);              \
            v_ = *(const float4*)(ap_ + k0_);                                    \
        }                                                                        \
        pa[slot] = v_;                                                           \
    } while (0)

#define LOAD_W_ELEM(slot, wrow, wc)                                              \
    do {                                                                         \
        int k0_ = kbn + (wc) * 4;                                                \
        int n_  = nb + (wrow);                                                   \
        float4 v_ = make_float4(0.f, 0.f, 0.f, 0.f);                             \
        if (n_ < N && k0_ + 4 <= ks1)                                            \
            v_ = *(const float4*)(W + (size_t)n_ * ldw + k0_);                   \
        pw[slot] = v_;                                                           \
    } while (0)

#define LOAD_ALL()                                                               \
    do {                                                                         \
        LOAD_A_ELEM(0, arow0, ac0);                                              \
        LOAD_A_ELEM(1, arow1, ac1);                                              \
        LOAD_W_ELEM(0, wrow0, wc0);                                              \
        LOAD_W_ELEM(1, wrow1, wc1);                                              \
        LOAD_W_ELEM(2, wrow2, wc2);                                              \
        LOAD_W_ELEM(3, wrow3, wc3);                                              \
    } while (0)

#define STORE_A(slot, arow, ac)                                                  \
    do {                                                                         \
        float4 v_ = pa[slot];                                                    \
        float hx_ = to_tf32(v_.x), hy_ = to_tf32(v_.y),                          \
              hz_ = to_tf32(v_.z), hw_ = to_tf32(v_.w);                          \
        As[0][arow][(ac) * 4 + 0] = hx_;                                         \
        As[0][arow][(ac) * 4 + 1] = hy_;                                         \
        As[0][arow][(ac) * 4 + 2] = hz_;                                         \
        As[0][arow][(ac) * 4 + 3] = hw_;                                         \
        As[1][arow][(ac) * 4 + 0] = to_tf32(v_.x - hx_);                         \
        As[1][arow][(ac) * 4 + 1] = to_tf32(v_.y - hy_);                         \
        As[1][arow][(ac) * 4 + 2] = to_tf32(v_.z - hz_);                         \
        As[1][arow][(ac) * 4 + 3] = to_tf32(v_.w - hw_);                         \
    } while (0)

#define STORE_W(slot, wrow, wc)                                                  \
    do {                                                                         \
        float4 v_ = pw[slot];                                                    \
        float hx_ = to_tf32(v_.x), hy_ = to_tf32(v_.y),                          \
              hz_ = to_tf32(v_.z), hw_ = to_tf32(v_.w);                          \
        Ws[0][wrow][(wc) * 4 + 0] = hx_;                                         \
        Ws[0][wrow][(wc) * 4 + 1] = hy_;                                         \
        Ws[0][wrow][(wc) * 4 + 2] = hz_;                                         \
        Ws[0][wrow][(wc) * 4 + 3] = hw_;                                         \
        Ws[1][wrow][(wc) * 4 + 0] = to_tf32(v_.x - hx_);                         \
        Ws[1][wrow][(wc) * 4 + 1] = to_tf32(v_.y - hy_);                         \
        Ws[1][wrow][(wc) * 4 + 2] = to_tf32(v_.z - hz_);                         \
        Ws[1][wrow][(wc) * 4 + 3] = to_tf32(v_.w - hw_);                         \
    } while (0)

    {
        int kbn = ks0;
        LOAD_ALL();
    }

    for (int kb = ks0; kb < ks1; kb += 32) {
        STORE_A(0, arow0, ac0);
        STORE_A(1, arow1, ac1);
        STORE_W(0, wrow0, wc0);
        STORE_W(1, wrow1, wc1);
        STORE_W(2, wrow2, wc2);
        STORE_W(3, wrow3, wc3);
        __syncthreads();

        if (kb + 32 < ks1) {
            int kbn = kb + 32;
            LOAD_ALL();
        }

#pragma unroll
        for (int kk = 0; kk < 32; kk += 8) {
            unsigned int ah[2][4], al[2][4];
#pragma unroll
            for (int tm = 0; tm < 2; tm++) {
                int m = warp_m * 32 + tm * 16;
                ah[tm][0] = __float_as_uint(As[0][m + g    ][kk + q    ]);
                ah[tm][1] = __float_as_uint(As[0][m + g + 8][kk + q    ]);
                ah[tm][2] = __float_as_uint(As[0][m + g    ][kk + q + 4]);
                ah[tm][3] = __float_as_uint(As[0][m + g + 8][kk + q + 4]);
                al[tm][0] = __float_as_uint(As[1][m + g    ][kk + q    ]);
                al[tm][1] = __float_as_uint(As[1][m + g + 8][kk + q    ]);
                al[tm][2] = __float_as_uint(As[1][m + g    ][kk + q + 4]);
                al[tm][3] = __float_as_uint(As[1][m + g + 8][kk + q + 4]);
            }
#pragma unroll
            for (int tn = 0; tn < 4; tn++) {
                int n = warp_n * 32 + tn * 8 + g;
                unsigned int bh0 = __float_as_uint(Ws[0][n][kk + q    ]);
                unsigned int bh1 = __float_as_uint(Ws[0][n][kk + q + 4]);
                unsigned int bl0 = __float_as_uint(Ws[1][n][kk + q    ]);
                unsigned int bl1 = __float_as_uint(Ws[1][n][kk + q + 4]);
#pragma unroll
                for (int tm = 0; tm < 2; tm++) {
                    asm volatile(
                        "mma.sync.aligned.m16n8k8.row.col.f32.tf32.tf32.f32 "
                        "{%0,%1,%2,%3}, {%4,%5,%6,%7}, {%8,%9}, {%0,%1,%2,%3};\n"
                        : "+f"(acc[tm][tn][0]), "+f"(acc[tm][tn][1]),
                          "+f"(acc[tm][tn][2]), "+f"(acc[tm][tn][3])
                        : "r"(al[tm][0]), "r"(al[tm][1]), "r"(al[tm][2]), "r"(al[tm][3]),
                          "r"(bh0), "r"(bh1));
                    asm volatile(
                        "mma.sync.aligned.m16n8k8.row.col.f32.tf32.tf32.f32 "
                        "{%0,%1,%2,%3}, {%4,%5,%6,%7}, {%8,%9}, {%0,%1,%2,%3};\n"
                        : "+f"(acc[tm][tn][0]), "+f"(acc[tm][tn][1]),
                          "+f"(acc[tm][tn][2]), "+f"(acc[tm][tn][3])
                        : "r"(ah[tm][0]), "r"(ah[tm][1]), "r"(ah[tm][2]), "r"(ah[tm][3]),
                          "r"(bl0), "r"(bl1));
                    asm volatile(
                        "mma.sync.aligned.m16n8k8.row.col.f32.tf32.tf32.f32 "
                        "{%0,%1,%2,%3}, {%4,%5,%6,%7}, {%8,%9}, {%0,%1,%2,%3};\n"
                        : "+f"(acc[tm][tn][0]), "+f"(acc[tm][tn][1]),
                          "+f"(acc[tm][tn][2]), "+f"(acc[tm][tn][3])
                        : "r"(ah[tm][0]), "r"(ah[tm][1]), "r"(ah[tm][2]), "r"(ah[tm][3]),
                          "r"(bh0), "r"(bh1));
                }
            }
        }
        __syncthreads();
    }

#undef LOAD_A_ELEM
#undef LOAD_W_ELEM
#undef LOAD_ALL
#undef STORE_A
#undef STORE_W

#pragma unroll
    for (int tm = 0; tm < 2; tm++) {
#pragma unroll
        for (int tn = 0; tn < 4; tn++) {
            int m0 = warp_m * 32 + tm * 16 + g;
            int n  = nb + warp_n * 32 + tn * 8 + q * 2;
            if (n < N) {
                *(float2*)(Cpart + (size_t)m0 * N + n) =
                    make_float2(acc[tm][tn][0], acc[tm][tn][1]);
                *(float2*)(Cpart + (size_t)(m0 + 8) * N + n) =
                    make_float2(acc[tm][tn][2], acc[tm][tn][3]);
            }
        }
    }
}

// ---------------- kernels ----------------
__global__ void __launch_bounds__(256) k_gru_gemm(
    const int* __restrict__ input, const float* __restrict__ emb,
    const float* __restrict__ hidden,
    const float* __restrict__ w_ih, const float* __restrict__ w_hh)
{
    int split = blockIdx.y;
    if (blockIdx.z == 0) {
        if (split >= SPL_GI) return;
        int ks0 = split * 64;
        int ks1 = min(ks0 + 64, EMBD);
        tf32_gemm(nullptr, EMBD, input, emb, true, w_ih, EMBD, G3H,
                  g_part_gi + (size_t)split * BB * G3H, ks0, ks1);
    } else {
        int ks0 = split * 128;
        int ks1 = ks0 + 128;
        tf32_gemm(hidden, HH, nullptr, nullptr, false, w_hh, HH, G3H,
                  g_part_gh + (size_t)split * BB * G3H, ks0, ks1);
    }
}

// GRU combine + gate math: float2, grid 128, block 256 (32768 threads)
__global__ void __launch_bounds__(256) k_gru(
    const float* __restrict__ hidden,
    const float* __restrict__ b_ih, const float* __restrict__ b_hh,
    float* __restrict__ out_hid)
{
    int idx2 = blockIdx.x * 256 + threadIdx.x;     // 0..32767
    int b  = idx2 >> 9;
    int j  = (idx2 & 511) * 2;

    float2 gir = *(const float2*)(b_ih + j);
    float2 giz = *(const float2*)(b_ih + j + HH);
    float2 gin = *(const float2*)(b_ih + j + 2 * HH);
    float2 ghr = *(const float2*)(b_hh + j);
    float2 ghz = *(const float2*)(b_hh + j + HH);
    float2 ghn = *(const float2*)(b_hh + j + 2 * HH);

#pragma unroll
    for (int s = 0; s < SPL_GI; s++) {
        const float* pi = g_part_gi + (size_t)s * BB * G3H + (size_t)b * G3H;
        float2 a = *(const float2*)(pi + j);
        float2 c = *(const float2*)(pi + j + HH);
        float2 d = *(const float2*)(pi + j + 2 * HH);
        gir.x += a.x; gir.y += a.y;
        giz.x += c.x; giz.y += c.y;
        gin.x += d.x; gin.y += d.y;
    }
#pragma unroll
    for (int s = 0; s < SPL_GH; s++) {
        const float* ph = g_part_gh + (size_t)s * BB * G3H + (size_t)b * G3H;
        float2 a = *(const float2*)(ph + j);
        float2 c = *(const float2*)(ph + j + HH);
        float2 d = *(const float2*)(ph + j + 2 * HH);
        ghr.x += a.x; ghr.y += a.y;
        ghz.x += c.x; ghz.y += c.y;
        ghn.x += d.x; ghn.y += d.y;
    }

    float2 hv = *(const float2*)(hidden + (size_t)b * HH + j);
    float2 hn;
    {
        float r0 = 1.f / (1.f + __expf(-(gir.x + ghr.x)));
        float z0 = 1.f / (1.f + __expf(-(giz.x + ghz.x)));
        float n0 = tanhf(gin.x + r0 * ghn.x);
        hn.x = (1.f - z0) * n0 + z0 * hv.x;
        float r1 = 1.f / (1.f + __expf(-(gir.y + ghr.y)));
        float z1 = 1.f / (1.f + __expf(-(giz.y + ghz.y)));
        float n1 = tanhf(gin.y + r1 * ghn.y);
        hn.y = (1.f - z1) * n1 + z1 * hv.y;
    }
    *(float2*)(g_hnew + (size_t)b * HH + j)         = hn;
    *(float2*)(g_cat + (size_t)b * 2 * HH + HH + j) = hn;
    *(float2*)(out_hid + (size_t)b * HH + j)        = hn;
}

__global__ void __launch_bounds__(256) k_gemm_wy(const float* __restrict__ w_attn)
{
    int split = blockIdx.y;
    int ks0 = split * 64;
    tf32_gemm(g_hnew, HH, nullptr, nullptr, false, w_attn, HH, HH,
              g_part_wy + (size_t)split * BB * HH, ks0, ks0 + 64);
}

// attention pass 1, persistent tiles: grid 256, each block = 4 chunks of ONE b.
// Single wave (256 <= 296 slots), perfect balance, Wy combine done once per block.
__global__ void __launch_bounds__(256) k_attn1(
    const float* __restrict__ src, const int* __restrict__ mask,
    const float* __restrict__ b_attn)
{
    int bid = blockIdx.x;              // 0..255
    int b = bid >> 2;                  // 0..63
    int chunk0 = (bid & 3) * 4;        // 0,4,8,12
    int tid = threadIdx.x, lane = tid & 31, wid = tid >> 5;

    __shared__ float swy[1024];
    __shared__ float sm[8], ss[8];
    __shared__ float sctx[8][1024];

    // fused combine (once per block): sum the 16 Wy partials for row b into smem
    {
        int h = tid * 4;
        float4 v = *(const float4*)(b_attn + h);
#pragma unroll
        for (int s = 0; s < SPL_WY; s++)
            v = f4_add(v, *(const float4*)(g_part_wy + (size_t)s * BB * HH
                                            + (size_t)b * HH + h));
        *(float4*)&swy[h] = v;
    }
    __syncthreads();

    float4 wyv[8];
#pragma unroll
    for (int qq = 0; qq < 8; qq++)
        wyv[qq] = *(const float4*)&swy[4 * lane + 128 * qq];

#pragma unroll 1
    for (int c = 0; c < 4; c++) {
        int chunk = chunk0 + c;
        int l0 = chunk * 64;

        float m = -1e30f, s = 0.f;
        float4 acc[8];
#pragma unroll
        for (int qq = 0; qq < 8; qq++) acc[qq] = make_float4(0.f, 0.f, 0.f, 0.f);

        for (int i = 0; i < 8; i++) {
            int l = l0 + wid * 8 + i;
            const float* sp = src + ((size_t)l * BB + b) * HH;
            float4 v[8];
#pragma unroll
            for (int qq = 0; qq < 8; qq++)
                v[qq] = *(const float4*)(sp + 4 * lane + 128 * qq);
            float d = 0.f;
#pragma unroll
            for (int qq = 0; qq < 8; qq++) {
                d = fmaf(v[qq].x, wyv[qq].x, d);
                d = fmaf(v[qq].y, wyv[qq].y, d);
                d = fmaf(v[qq].z, wyv[qq].z, d);
                d = fmaf(v[qq].w, wyv[qq].w, d);
            }
#pragma unroll
            for (int o = 16; o > 0; o >>= 1) d += __shfl_xor_sync(0xffffffffu, d, o);
            if (mask[(size_t)b * LL + l] != 0) d = -1e30f;
            if (lane == 0) g_xwy[(size_t)b * LL + l] = d;

            float nm = fmaxf(m, d);
            float sc = __expf(m - nm);
            float p  = __expf(d - nm);
            s = s * sc + p;
#pragma unroll
            for (int qq = 0; qq < 8; qq++) {
                acc[qq].x = acc[qq].x * sc + p * v[qq].x;
                acc[qq].y = acc[qq].y * sc + p * v[qq].y;
                acc[qq].z = acc[qq].z * sc + p * v[qq].z;
                acc[qq].w = acc[qq].w * sc + p * v[qq].w;
            }
            m = nm;
        }

        if (lane == 0) { sm[wid] = m; ss[wid] = s; }
        __syncthreads();
        float M = sm[0];
#pragma unroll
        for (int w = 1; w < 8; w++) M = fmaxf(M, sm[w]);
        float S = 0.f;
#pragma unroll
        for (int w = 0; w < 8; w++) S += ss[w] * __expf(sm[w] - M);

        float f = __expf(m - M);
#pragma unroll
        for (int qq = 0; qq < 8; qq++) {
            float4 t = acc[qq];
            t.x *= f; t.y *= f; t.z *= f; t.w *= f;
            *(float4*)&sctx[wid][4 * lane + 128 * qq] = t;
        }
        __syncthreads();

        int h0 = tid * 4;
        float4 tot = make_float4(0.f, 0.f, 0.f, 0.f);
#pragma unroll
        for (int w = 0; w < 8; w++) {
            float4 t = *(const float4*)&sctx[w][h0];
            tot.x += t.x; tot.y += t.y; tot.z += t.z; tot.w += t.w;
        }
        int pidx = b * 16 + chunk;
        *(float4*)(g_pctx + (size_t)pidx * HH + h0) = tot;
        if (tid == 0) { g_pm[pidx] = M; g_ps[pidx] = S; }
        __syncthreads();   // smem (sm/ss/sctx) reused next chunk
    }
}

__global__ void k_attn2(float* __restrict__ out_scores)
{
    int b = blockIdx.x, t = threadIdx.x;
    __shared__ float fac[16];
    __shared__ float sM, sInvZ;
    if (t == 0) {
        float M = g_pm[b * 16];
        for (int c = 1; c < 16; c++) M = fmaxf(M, g_pm[b * 16 + c]);
        float Z = 0.f;
        for (int c = 0; c < 16; c++) Z += g_ps[b * 16 + c] * __expf(g_pm[b * 16 + c] - M);
        float invZ = 1.f / Z;
        for (int c = 0; c < 16; c++) fac[c] = __expf(g_pm[b * 16 + c] - M) * invZ;
        sM = M; sInvZ = invZ;
    }
    __syncthreads();

    int h0 = t * 4;
    float4 tot = make_float4(0.f, 0.f, 0.f, 0.f);
#pragma unroll
    for (int c = 0; c < 16; c++) {
        float4 v = *(const float4*)(g_pctx + (size_t)(b * 16 + c) * HH + h0);
        float fc = fac[c];
        tot.x += v.x * fc; tot.y += v.y * fc; tot.z += v.z * fc; tot.w += v.w * fc;
    }
    *(float4*)(g_cat + (size_t)b * 2 * HH + h0) = tot;

    float M = sM, invZ = sInvZ;
#pragma unroll
    for (int r = 0; r < 4; r++) {
        int l = t + 256 * r;
        float sc = __expf(g_xwy[(size_t)b * LL + l] - M) * invZ;
        out_scores[(size_t)b * LL + l] = sc;
    }
}

__global__ void __launch_bounds__(256) k_gemm_fu(const float* __restrict__ w_lin)
{
    int split = blockIdx.y;
    int ks0 = split * 128;
    tf32_gemm(g_cat, 2 * HH, nullptr, nullptr, false, w_lin, 2 * HH, HH,
              g_part_fu + (size_t)split * BB * HH, ks0, ks0 + 128);
}

// combine + tanh + bf16: float2, grid 128, block 256 (32768 threads)
__global__ void __launch_bounds__(256) k_combine_fu(const float* __restrict__ b_lin)
{
    int idx2 = blockIdx.x * 256 + threadIdx.x;
    int j = (idx2 & 511) * 2;
    int off = (idx2 >> 9) * HH + j;
    float2 v = *(const float2*)(b_lin + j);
#pragma unroll
    for (int s = 0; s < SPL_FU; s++) {
        float2 p = *(const float2*)(g_part_fu + (size_t)s * BB * HH + off);
        v.x += p.x; v.y += p.y;
    }
    __nv_bfloat162 pk = __floats2bfloat162_rn(tanhf(v.x), tanhf(v.y));
    *(unsigned int*)(g_fused_b16 + off) = *(unsigned int*)&pk;
}

// ---------------- logits GEMM on tensor cores (bf16, BN=128) + fused per-block LSE ----
// R14-exact version.
#define LBK 64
#define WPAD 72

__global__ void __launch_bounds__(256) k_logits_mma(
    const float* __restrict__ w_out, const float* __restrict__ b_out,
    float* __restrict__ out_logp)
{
    __shared__ __nv_bfloat16 As[64][WPAD];
    __shared__ __nv_bfloat16 Ws[LBN][WPAD];
    __shared__ float sRm[4][64], sRs[4][64];

    const int tid  = threadIdx.x;
    const int lane = tid & 31;
    const int wid  = tid >> 5;
    const int nb   = blockIdx.x * LBN;
    const int warp_m = wid >> 2;
    const int warp_n = wid & 3;
    const int g = lane >> 2;
    const int q = lane & 3;

    float acc[2][4][4];
#pragma unroll
    for (int tm = 0; tm < 2; tm++)
#pragma unroll
        for (int tn = 0; tn < 4; tn++)
#pragma unroll
            for (int c = 0; c < 4; c++) acc[tm][tn][c] = 0.f;

    const int ar = tid >> 2;
    const int as = tid & 3;
    const int wr = tid >> 2;
    const int wc = tid & 3;

    uint4 pa0, pa1;
    float4 pw[8];

    {
        const uint4* s4 = (const uint4*)(g_fused_b16 + (size_t)ar * HH + as * 16);
        pa0 = s4[0]; pa1 = s4[1];
#pragma unroll
        for (int half = 0; half < 2; half++) {
            int n = nb + wr + half * 64;
            const float* wp = w_out + (size_t)n * HH;
            bool ok = (n < VV);
#pragma unroll
            for (int j = 0; j < 4; j++) {
                int f4 = wc + j * 4;
                pw[half * 4 + j] = ok ? *(const float4*)(wp + f4 * 4)
                                      : make_float4(0.f, 0.f, 0.f, 0.f);
            }
        }
    }

    for (int kb = 0; kb < HH; kb += LBK) {
        *(uint4*)(&As[ar][as * 16])     = pa0;
        *(uint4*)(&As[ar][as * 16 + 8]) = pa1;
#pragma unroll
        for (int half = 0; half < 2; half++) {
#pragma unroll
            for (int j = 0; j < 4; j++) {
                int f4 = wc + j * 4;
                float4 v = pw[half * 4 + j];
                __nv_bfloat162 p0 = __floats2bfloat162_rn(v.x, v.y);
                __nv_bfloat162 p1 = __floats2bfloat162_rn(v.z, v.w);
                uint2 pk;
                pk.x = *(unsigned int*)&p0;
                pk.y = *(unsigned int*)&p1;
                *(uint2*)(&Ws[wr + half * 64][f4 * 4]) = pk;
            }
        }
        __syncthreads();

        if (kb + LBK < HH) {
            int kn = kb + LBK;
            const uint4* s4 = (const uint4*)(g_fused_b16 + (size_t)ar * HH + kn + as * 16);
            pa0 = s4[0]; pa1 = s4[1];
#pragma unroll
            for (int half = 0; half < 2; half++) {
                int n = nb + wr + half * 64;
                const float* wp = w_out + (size_t)n * HH + kn;
                bool ok = (n < VV);
#pragma unroll
                for (int j = 0; j < 4; j++) {
                    int f4 = wc + j * 4;
                    pw[half * 4 + j] = ok ? *(const float4*)(wp + f4 * 4)
                                          : make_float4(0.f, 0.f, 0.f, 0.f);
                }
            }
        }

#pragma unroll
        for (int kk = 0; kk < LBK; kk += 16) {
            unsigned int a[2][4];
#pragma unroll
            for (int tm = 0; tm < 2; tm++) {
                int m = warp_m * 32 + tm * 16;
                a[tm][0] = *(const unsigned int*)&As[m + g    ][kk + q * 2];
                a[tm][1] = *(const unsigned int*)&As[m + g + 8][kk + q * 2];
                a[tm][2] = *(const unsigned int*)&As[m + g    ][kk + 8 + q * 2];
                a[tm][3] = *(const unsigned int*)&As[m + g + 8][kk + 8 + q * 2];
            }
#pragma unroll
            for (int tn = 0; tn < 4; tn++) {
                int n = warp_n * 32 + tn * 8;
                unsigned int b0 = *(const unsigned int*)&Ws[n + g][kk + q * 2];
                unsigned int b1 = *(const unsigned int*)&Ws[n + g][kk + 8 + q * 2];
#pragma unroll
                for (int tm = 0; tm < 2; tm++) {
                    asm volatile(
                        "mma.sync.aligned.m16n8k16.row.col.f32.bf16.bf16.f32 "
                        "{%0,%1,%2,%3}, {%4,%5,%6,%7}, {%8,%9}, {%0,%1,%2,%3};\n"
                        : "+f"(acc[tm][tn][0]), "+f"(acc[tm][tn][1]),
                          "+f"(acc[tm][tn][2]), "+f"(acc[tm][tn][3])
                        : "r"(a[tm][0]), "r"(a[tm][1]), "r"(a[tm][2]), "r"(a[tm][3]),
                          "r"(b0), "r"(b1));
                }
            }
        }
        __syncthreads();
    }

    // epilogue: bias + store + per-row partial logsumexp over this block's 128 cols
    float rm[4], rs[4];
#pragma unroll
    for (int k = 0; k < 4; k++) { rm[k] = -1e30f; rs[k] = 0.f; }

#pragma unroll
    for (int tm = 0; tm < 2; tm++) {
#pragma unroll
        for (int tn = 0; tn < 4; tn++) {
            int m0 = warp_m * 32 + tm * 16 + g;
            int n  = nb + warp_n * 32 + tn * 8 + q * 2;
            bool ok0 = (n < VV), ok1 = (n + 1 < VV);
            float bz0 = ok0 ? b_out[n] : 0.f;
            float bz1 = ok1 ? b_out[n + 1] : 0.f;
            float v00 = acc[tm][tn][0] + bz0, v01 = acc[tm][tn][1] + bz1;
            float v10 = acc[tm][tn][2] + bz0, v11 = acc[tm][tn][3] + bz1;
            if (ok1) {
                *(float2*)(out_logp + (size_t)m0 * VV + n)       = make_float2(v00, v01);
                *(float2*)(out_logp + (size_t)(m0 + 8) * VV + n) = make_float2(v10, v11);
            } else if (ok0) {
                out_logp[(size_t)m0 * VV + n]       = v00;
                out_logp[(size_t)(m0 + 8) * VV + n] = v10;
            }
            int k0 = tm * 2, k1 = tm * 2 + 1;
            if (ok0) { lse_upd(rm[k0], rs[k0], v00); lse_upd(rm[k1], rs[k1], v10); }
            if (ok1) { lse_upd(rm[k0], rs[k0], v01); lse_upd(rm[k1], rs[k1], v11); }
        }
    }

#pragma unroll
    for (int k = 0; k < 4; k++) {
#pragma unroll
        for (int o = 1; o <= 2; o <<= 1) {
            float m2 = __shfl_xor_sync(0xffffffffu, rm[k], o);
            float s2 = __shfl_xor_sync(0xffffffffu, rs[k], o);
            lse_merge(rm[k], rs[k], m2, s2);
        }
    }
    if (q == 0) {
#pragma unroll
        for (int k = 0; k < 4; k++) {
            int row = warp_m * 32 + (k >> 1) * 16 + (k & 1) * 8 + g;
            sRm[warp_n][row] = rm[k];
            sRs[warp_n][row] = rs[k];
        }
    }
    __syncthreads();
    if (tid < 64) {
        float M = sRm[0][tid], S = sRs[0][tid];
#pragma unroll
        for (int w = 1; w < 4; w++) lse_merge(M, S, sRm[w][tid], sRs[w][tid]);
        g_lsm[(size_t)tid * NBLKP + blockIdx.x] = M;
        g_lss[(size_t)tid * NBLKP + blockIdx.x] = S;
    }
}

// final: reduce the NBLK per-block LSE partials, subtract. grid (49, 64), block 256
__global__ void k_sub(float* __restrict__ logp)
{
    __shared__ float slse;
    __shared__ float smW[8], ssW[8];
    int b = blockIdx.y;
    int t = threadIdx.x;

    float m = -1e30f, s = 0.f;
    for (int i = t; i < NBLK; i += 256)
        lse_merge(m, s, g_lsm[(size_t)b * NBLKP + i], g_lss[(size_t)b * NBLKP + i]);
#pragma unroll
    for (int o = 16; o > 0; o >>= 1) {
        float m2 = __shfl_xor_sync(0xffffffffu, m, o);
        float s2 = __shfl_xor_sync(0xffffffffu, s, o);
        lse_merge(m, s, m2, s2);
    }
    int lane = t & 31, wid = t >> 5;
    if (lane == 0) { smW[wid] = m; ssW[wid] = s; }
    __syncthreads();
    if (t == 0) {
        float M = smW[0], S = ssW[0];
#pragma unroll
        for (int w = 1; w < 8; w++) lse_merge(M, S, smW[w], ssW[w]);
        slse = M + logf(S);
    }
    __syncthreads();

    int n4 = blockIdx.x * 256 + t;
    if (n4 < VV4) {
        float l = slse;
        float4* p = (float4*)(logp + (size_t)b * VV) + n4;
        float4 v = *p;
        v.x -= l; v.y -= l; v.z -= l; v.w -= l;
        *p = v;
    }
}

// ---------------- launcher ----------------
extern "C" void kernel_launch(void* const* d_in, const int* in_sizes, int n_in,
                              void* d_out, int out_size)
{
    const int*   input  = (const int*)  d_in[0];
    const float* hidden = (const float*)d_in[1];
    const float* src    = (const float*)d_in[2];
    const int*   mask   = (const int*)  d_in[3];
    const float* emb    = (const float*)d_in[4];
    const float* w_ih   = (const float*)d_in[5];
    const float* w_hh   = (const float*)d_in[6];
    const float* b_ih   = (const float*)d_in[7];
    const float* b_hh   = (const float*)d_in[8];
    const float* w_attn = (const float*)d_in[9];
    const float* b_attn = (const float*)d_in[10];
    const float* w_lin  = (const float*)d_in[11];
    const float* b_lin  = (const float*)d_in[12];
    const float* w_out  = (const float*)d_in[13];
    const float* b_out  = (const float*)d_in[14];

    float* out        = (float*)d_out;
    float* out_logp   = out;                                   // [64 x 50004]
    float* out_hid    = out + (size_t)BB * VV;                 // [1 x 64 x 1024]
    float* out_scores = out_hid + (size_t)BB * HH;             // [64 x 1024]

    k_gru_gemm<<<dim3(24, 8, 2), 256>>>(input, emb, hidden, w_ih, w_hh);
    k_gru<<<128, 256>>>(hidden, b_ih, b_hh, out_hid);
    k_gemm_wy<<<dim3(8, SPL_WY), 256>>>(w_attn);
    k_attn1<<<256, 256>>>(src, mask, b_attn);
    k_attn2<<<BB, 256>>>(out_scores);
    k_gemm_fu<<<dim3(8, SPL_FU), 256>>>(w_lin);
    k_combine_fu<<<128, 256>>>(b_lin);
    k_logits_mma<<<NBLK, 256>>>(w_out, b_out, out_logp);
    k_sub<<<dim3((VV4 + 255) / 256, BB), 256>>>(out_logp);
}